// round 3
// baseline (speedup 1.0000x reference)
#include <cuda_runtime.h>
#include <cstddef>

#define CIN 128
#define HH  112
#define WW  112
#define OHH 56
#define OWW 56
#define NB  8

// scratch: normalized sigma, (8, 9, 56, 56) f32 = 3.6 MB
__device__ float g_sigma[(size_t)NB * 9 * OHH * OWW];

// ---------------------------------------------------------------------------
// Kernel 1: sigma at strided positions only.
// Block = 8x8 output tile of one image. 256 threads = 8 channel-groups(16ch)
// x 32 position-pairs. Weights staged to smem as ws[c][tap][12] (sc-contig).
// smem: ws 13824 f + part 4608 f + red 576 f = 19008 f = 76032 B (dynamic).
// ---------------------------------------------------------------------------
__global__ void __launch_bounds__(256)
pasa_sigma_kernel(const float* __restrict__ x,
                  const float* __restrict__ cw,
                  const float* __restrict__ bnw,
                  const float* __restrict__ bnb,
                  const float* __restrict__ bnm,
                  const float* __restrict__ bnv)
{
    extern __shared__ float sm[];
    float* ws   = sm;            // [128][9][12]
    float* part = sm + 13824;    // [64*9][8]
    float* red  = part + 4608;   // [576]

    const int n   = blockIdx.y;
    const int t   = blockIdx.x;            // 0..48
    const int oh0 = (t / 7) * 8;
    const int ow0 = (t - (t / 7) * 7) * 8;
    const int tid = threadIdx.x;

    // stage weights: cw[sc][c][tap] -> ws[c*108 + tap*12 + sc]
    for (int i = tid; i < 10368; i += 256) {
        int sc  = i / 1152;
        int r   = i - sc * 1152;
        int c   = r / 9;
        int tap = r - c * 9;
        ws[c * 108 + tap * 12 + sc] = cw[i];
    }
    __syncthreads();

    const int g   = tid >> 5;          // channel group 0..7 (16 ch each)
    const int p   = tid & 31;          // position-pair 0..31
    const int py  = p >> 2;            // 0..7
    const int pxp = p & 3;             // 0..3 -> ow pair (2*pxp, 2*pxp+1)
    const int oh  = oh0 + py;
    const int ow  = ow0 + pxp * 2;

    float acc0[9], acc1[9];
#pragma unroll
    for (int s = 0; s < 9; ++s) { acc0[s] = 0.f; acc1[s] = 0.f; }

    // reflect only needed at -1 for strided positions (max index is 111)
    int ihs[3], iws[5];
#pragma unroll
    for (int r = 0; r < 3; ++r) { int v = 2 * oh - 1 + r; ihs[r] = v < 0 ? -v : v; }
#pragma unroll
    for (int q = 0; q < 5; ++q) { int v = 2 * ow - 1 + q; iws[q] = v < 0 ? -v : v; }

    const float* xn = x + (size_t)n * CIN * HH * WW;

    for (int cc = 0; cc < 16; ++cc) {
        const int c = g * 16 + cc;
        const float* xc = xn + (size_t)c * HH * WW;
        float xv[3][5];
#pragma unroll
        for (int r = 0; r < 3; ++r) {
            const float* xr = xc + ihs[r] * WW;
#pragma unroll
            for (int q = 0; q < 5; ++q) xv[r][q] = __ldg(xr + iws[q]);
        }
        const float* wc = ws + c * 108;
#pragma unroll
        for (int r = 0; r < 3; ++r) {
#pragma unroll
            for (int j = 0; j < 3; ++j) {
                const float* wt = wc + (r * 3 + j) * 12;
                const float4 wa = *(const float4*)(wt);
                const float4 wb = *(const float4*)(wt + 4);
                const float  w8 = wt[8];
                const float xa = xv[r][j];       // position ow
                const float xb = xv[r][j + 2];   // position ow+1
                acc0[0] += xa * wa.x;  acc1[0] += xb * wa.x;
                acc0[1] += xa * wa.y;  acc1[1] += xb * wa.y;
                acc0[2] += xa * wa.z;  acc1[2] += xb * wa.z;
                acc0[3] += xa * wa.w;  acc1[3] += xb * wa.w;
                acc0[4] += xa * wb.x;  acc1[4] += xb * wb.x;
                acc0[5] += xa * wb.y;  acc1[5] += xb * wb.y;
                acc0[6] += xa * wb.z;  acc1[6] += xb * wb.z;
                acc0[7] += xa * wb.w;  acc1[7] += xb * wb.w;
                acc0[8] += xa * w8;    acc1[8] += xb * w8;
            }
        }
    }

    const int pos0 = py * 8 + pxp * 2;
#pragma unroll
    for (int s = 0; s < 9; ++s) {
        part[(pos0 * 9 + s) * 8 + g]       = acc0[s];
        part[((pos0 + 1) * 9 + s) * 8 + g] = acc1[s];
    }
    __syncthreads();

    // reduce 8 groups, BN, clamp
    for (int i = tid; i < 576; i += 256) {
        float ssum = 0.f;
#pragma unroll
        for (int gg = 0; gg < 8; ++gg) ssum += part[i * 8 + gg];
        const int sc = i % 9;
        const float scl = __ldg(bnw + sc) * rsqrtf(__ldg(bnv + sc) + 1e-5f);
        const float sh  = __ldg(bnb + sc) - __ldg(bnm + sc) * scl;
        red[i] = fmaxf(ssum * scl + sh, 1e-4f);
    }
    __syncthreads();

    // normalize per position, write to global sigma
    if (tid < 64) {
        const int pos = tid;
        float s = 0.f;
#pragma unroll
        for (int sc = 0; sc < 9; ++sc) s += red[pos * 9 + sc];
        const float inv = 1.f / s;
        const int oy = oh0 + (pos >> 3);
        const int ox = ow0 + (pos & 7);
        float* sg = g_sigma + (size_t)n * 9 * OHH * OWW + oy * OWW + ox;
#pragma unroll
        for (int sc = 0; sc < 9; ++sc)
            sg[(size_t)sc * OHH * OWW] = red[pos * 9 + sc] * inv;
    }
}

// ---------------------------------------------------------------------------
// Kernel 2: apply sigma. 224 threads = 4 output rows x 56. grid (14,128,8).
// ---------------------------------------------------------------------------
__global__ void __launch_bounds__(224)
pasa_apply_kernel(const float* __restrict__ x, float* __restrict__ out)
{
    const int n   = blockIdx.z;
    const int c   = blockIdx.y;
    const int tid = threadIdx.x;
    const int oh  = blockIdx.x * 4 + tid / OWW;
    const int ow  = tid - (tid / OWW) * OWW;

    const float* xc = x + ((size_t)(n * CIN + c)) * HH * WW;
    const float* sg = g_sigma + (size_t)n * 9 * OHH * OWW + oh * OWW + ow;

    const int ihb = 2 * oh - 1;
    const int iwb = 2 * ow - 1;
    float r = 0.f;
#pragma unroll
    for (int i = 0; i < 3; ++i) {
        int ih = ihb + i; ih = ih < 0 ? -ih : ih;
        const float* xr = xc + ih * WW;
#pragma unroll
        for (int j = 0; j < 3; ++j) {
            int iw = iwb + j; iw = iw < 0 ? -iw : iw;
            r += __ldg(xr + iw) * __ldg(sg + (size_t)(i * 3 + j) * OHH * OWW);
        }
    }
    out[((size_t)(n * CIN + c)) * OHH * OWW + oh * OWW + ow] = r;
}

extern "C" void kernel_launch(void* const* d_in, const int* in_sizes, int n_in,
                              void* d_out, int out_size)
{
    const float* x   = (const float*)d_in[0];
    const float* cw  = (const float*)d_in[1];
    const float* bnw = (const float*)d_in[2];
    const float* bnb = (const float*)d_in[3];
    const float* bnm = (const float*)d_in[4];
    const float* bnv = (const float*)d_in[5];
    float* out = (float*)d_out;

    const int smem1 = 19008 * sizeof(float);  // 76032 B
    cudaFuncSetAttribute(pasa_sigma_kernel,
                         cudaFuncAttributeMaxDynamicSharedMemorySize, smem1);

    dim3 g1(49, NB, 1);
    pasa_sigma_kernel<<<g1, 256, smem1>>>(x, cw, bnw, bnb, bnm, bnv);

    dim3 g2(14, CIN, NB);
    pasa_apply_kernel<<<g2, 224>>>(x, out);
}

// round 4
// speedup vs baseline: 1.3124x; 1.3124x over previous
#include <cuda_runtime.h>
#include <cstddef>

#define CIN 128
#define HH  112
#define WW  112
#define OHH 56
#define OWW 56
#define NB  8

typedef unsigned long long ull;

__device__ __forceinline__ ull pack2(float a, float b) {
    ull r; asm("mov.b64 %0, {%1, %2};" : "=l"(r) : "f"(a), "f"(b)); return r;
}
__device__ __forceinline__ void unpack2(ull v, float& a, float& b) {
    asm("mov.b64 {%0, %1}, %2;" : "=f"(a), "=f"(b) : "l"(v));
}
__device__ __forceinline__ void ffma2(ull& acc, ull x, ull w) {
    asm("fma.rn.f32x2 %0, %1, %2, %0;" : "+l"(acc) : "l"(x), "l"(w));
}

// normalized sigma scratch: (8, 9, 56, 56) f32 = 3.6 MB
__device__ float g_sigma[(size_t)NB * 9 * OHH * OWW];

// ---------------------------------------------------------------------------
// Kernel 1: sigma at strided positions.
// CTA = 8x8 output tile. 256 thr = 8 warps; warp w owns channels 16w..16w+15,
// lanes = 32 position-pairs (8 oh x 4 ow-pairs). Weight LDS is warp-broadcast.
// f32x2 packed FMA over sc-pairs.
// smem: ws[128][9][12]=13824f, part[8][592]=4736f, red 576f, pad -> 76,672 B
// ---------------------------------------------------------------------------
#define WS_F   13824
#define PART_F 4736
#define PART_STRIDE 592
#define SM1_F  (WS_F + PART_F + 576 + 16)

__global__ void __launch_bounds__(256)
pasa_sigma_kernel(const float* __restrict__ x,
                  const float* __restrict__ cw,
                  const float* __restrict__ bnw,
                  const float* __restrict__ bnb,
                  const float* __restrict__ bnm,
                  const float* __restrict__ bnv)
{
    extern __shared__ float sm[];
    float* ws   = sm;                    // [c][tap][12] (sc contiguous, pad 3)
    float* part = sm + WS_F;             // [8 warp][592]
    float* red  = part + PART_F;         // [576]

    const int n   = blockIdx.y;
    const int t   = blockIdx.x;               // 0..48
    const int oh0 = (t / 7) * 8;
    const int ow0 = (t - (t / 7) * 7) * 8;
    const int tid = threadIdx.x;

    // stage weights: cw[sc][c][tap] -> ws[c*108 + tap*12 + sc]
    for (int i = tid; i < 10368; i += 256) {
        int sc  = i / 1152;
        int r   = i - sc * 1152;
        int c   = r / 9;
        int tap = r - c * 9;
        ws[c * 108 + tap * 12 + sc] = cw[i];
    }
    __syncthreads();

    const int w    = tid >> 5;           // warp = channel group (16 ch)
    const int lane = tid & 31;
    const int ohl  = lane >> 2;          // 0..7
    const int owg  = lane & 3;           // 0..3 -> ow pair (2*owg, 2*owg+1)
    const int oh   = oh0 + ohl;

    // input coords: rows 2*oh-1..+1 (reflect at -1), cols iwb..iwb+4
    int ihs[3];
#pragma unroll
    for (int r = 0; r < 3; ++r) { int v = 2 * oh - 1 + r; ihs[r] = v < 0 ? -v : v; }
    const int iwb  = 2 * ow0 + 4 * owg - 1;          // may be -1
    const int iws0 = iwb < 0 ? 1 : iwb;              // reflected scalar col
    const int iwv  = iwb + 1;                        // float4 col (mult of 4)

    const float* xn = x + (size_t)n * CIN * HH * WW + (size_t)(w * 16) * HH * WW;

    // accumulators: 2 positions x (4 sc-pairs + 1 scalar)
    ull  a01 = 0, a23 = 0, a45 = 0, a67 = 0;  float a8 = 0.f;
    ull  b01 = 0, b23 = 0, b45 = 0, b67 = 0;  float b8 = 0.f;

#pragma unroll 2
    for (int cc = 0; cc < 16; ++cc) {
        const float* xc = xn + (size_t)cc * HH * WW;
        float xv[3][5];
#pragma unroll
        for (int r = 0; r < 3; ++r) {
            const float* xr = xc + ihs[r] * WW;
            xv[r][0] = __ldg(xr + iws0);
            const float4 v4 = *(const float4*)(xr + iwv);
            xv[r][1] = v4.x; xv[r][2] = v4.y; xv[r][3] = v4.z; xv[r][4] = v4.w;
        }
        const float* wc = ws + (w * 16 + cc) * 108;
#pragma unroll
        for (int r = 0; r < 3; ++r) {
#pragma unroll
            for (int j = 0; j < 3; ++j) {
                const float* wt = wc + (r * 3 + j) * 12;
                const ull* wp = (const ull*)wt;
                const ull w01 = wp[0], w23 = wp[1], w45 = wp[2], w67 = wp[3];
                const float w8 = wt[8];
                const float xa = xv[r][j];
                const float xb = xv[r][j + 2];
                const ull xda = pack2(xa, xa);
                const ull xdb = pack2(xb, xb);
                ffma2(a01, xda, w01); ffma2(a23, xda, w23);
                ffma2(a45, xda, w45); ffma2(a67, xda, w67);
                a8 += xa * w8;
                ffma2(b01, xdb, w01); ffma2(b23, xdb, w23);
                ffma2(b45, xdb, w45); ffma2(b67, xdb, w67);
                b8 += xb * w8;
            }
        }
    }

    // spill partials: part[w][pos*9 + sc]
    {
        float s[9];
        unpack2(a01, s[0], s[1]); unpack2(a23, s[2], s[3]);
        unpack2(a45, s[4], s[5]); unpack2(a67, s[6], s[7]); s[8] = a8;
        float* pa = part + w * PART_STRIDE + (ohl * 8 + 2 * owg) * 9;
#pragma unroll
        for (int sc = 0; sc < 9; ++sc) pa[sc] = s[sc];
        unpack2(b01, s[0], s[1]); unpack2(b23, s[2], s[3]);
        unpack2(b45, s[4], s[5]); unpack2(b67, s[6], s[7]); s[8] = b8;
        float* pb = pa + 9;
#pragma unroll
        for (int sc = 0; sc < 9; ++sc) pb[sc] = s[sc];
    }
    __syncthreads();

    // reduce 8 warps, BN, clamp -> red[pos*9+sc]
    for (int i = tid; i < 576; i += 256) {
        float ssum = 0.f;
#pragma unroll
        for (int g = 0; g < 8; ++g) ssum += part[g * PART_STRIDE + i];
        const int sc = i % 9;
        const float scl = __ldg(bnw + sc) * rsqrtf(__ldg(bnv + sc) + 1e-5f);
        const float sh  = __ldg(bnb + sc) - __ldg(bnm + sc) * scl;
        red[i] = fmaxf(ssum * scl + sh, 1e-4f);
    }
    __syncthreads();

    // normalize per position, write sigma[n][sc][oh][ow]
    if (tid < 64) {
        const int pos = tid;
        float s = 0.f;
#pragma unroll
        for (int sc = 0; sc < 9; ++sc) s += red[pos * 9 + sc];
        const float inv = 1.f / s;
        const int oy = oh0 + (pos >> 3);
        const int ox = ow0 + (pos & 7);
        float* sg = g_sigma + ((size_t)n * 9 * OHH + oy) * OWW + ox;
#pragma unroll
        for (int sc = 0; sc < 9; ++sc)
            sg[(size_t)sc * OHH * OWW] = red[pos * 9 + sc] * inv;
    }
}

// ---------------------------------------------------------------------------
// Kernel 2: apply sigma. Thread = 4 consecutive ow of one (n,c,oh).
// block 224 = 16 oh-rows x 14 ow-groups; grid (4, 128, 8), oh guarded.
// ---------------------------------------------------------------------------
__global__ void __launch_bounds__(224)
pasa_apply_kernel(const float* __restrict__ x, float* __restrict__ out)
{
    const int n   = blockIdx.z;
    const int c   = blockIdx.y;
    const int tid = threadIdx.x;
    const int r   = tid / 14;
    const int owg = tid - r * 14;
    const int oh  = blockIdx.x * 16 + r;
    if (oh >= OHH) return;
    const int ow0 = owg * 4;

    const float* xc = x + ((size_t)(n * CIN + c)) * HH * WW;
    const int iwb  = 8 * owg - 1;                 // -1 only when owg==0
    const int iws0 = iwb < 0 ? 1 : iwb;
    const int iwv  = iwb + 1;                     // multiple of 8 -> aligned

    // load 3 rows x 9 consecutive cols
    float xr[3][9];
#pragma unroll
    for (int i = 0; i < 3; ++i) {
        int ih = 2 * oh - 1 + i; ih = ih < 0 ? -ih : ih;
        const float* row = xc + ih * WW;
        xr[i][0] = __ldg(row + iws0);
        const float4 va = *(const float4*)(row + iwv);
        const float4 vb = *(const float4*)(row + iwv + 4);
        xr[i][1] = va.x; xr[i][2] = va.y; xr[i][3] = va.z; xr[i][4] = va.w;
        xr[i][5] = vb.x; xr[i][6] = vb.y; xr[i][7] = vb.z; xr[i][8] = vb.w;
    }

    const float* sg = g_sigma + ((size_t)n * 9 * OHH + oh) * OWW + ow0;
    float o0 = 0.f, o1 = 0.f, o2 = 0.f, o3 = 0.f;
#pragma unroll
    for (int i = 0; i < 3; ++i) {
#pragma unroll
        for (int j = 0; j < 3; ++j) {
            const float4 s4 = *(const float4*)(sg + (size_t)(i * 3 + j) * OHH * OWW);
            o0 += xr[i][j]     * s4.x;
            o1 += xr[i][j + 2] * s4.y;
            o2 += xr[i][j + 4] * s4.z;
            o3 += xr[i][j + 6] * s4.w;
        }
    }
    float4 o = make_float4(o0, o1, o2, o3);
    *(float4*)(out + ((size_t)(n * CIN + c) * OHH + oh) * OWW + ow0) = o;
}

extern "C" void kernel_launch(void* const* d_in, const int* in_sizes, int n_in,
                              void* d_out, int out_size)
{
    const float* x   = (const float*)d_in[0];
    const float* cw  = (const float*)d_in[1];
    const float* bnw = (const float*)d_in[2];
    const float* bnb = (const float*)d_in[3];
    const float* bnm = (const float*)d_in[4];
    const float* bnv = (const float*)d_in[5];
    float* out = (float*)d_out;

    const int smem1 = SM1_F * sizeof(float);
    cudaFuncSetAttribute(pasa_sigma_kernel,
                         cudaFuncAttributeMaxDynamicSharedMemorySize, smem1);

    dim3 g1(49, NB, 1);
    pasa_sigma_kernel<<<g1, 256, smem1>>>(x, cw, bnw, bnb, bnm, bnv);

    dim3 g2(4, CIN, NB);
    pasa_apply_kernel<<<g2, 224>>>(x, out);
}